// round 13
// baseline (speedup 1.0000x reference)
#include <cuda_runtime.h>
#include <cuda_fp16.h>
#include <cstdint>
#include <math.h>

#define NN 50000
#define FF 16
#define TT 12
#define HH 64
#define EE 1600000
#define CHX 192   // F*T channels of x per node
#define SCAN_B 49 // ceil(NN/1024)
#define EPAD (EE + NN)

// ---------------- scratch (static device arrays; no allocation) ----------------
__device__ float g_deg[NN];
__device__ float g_dis[NN];
__device__ float g_self[NN];
__device__ int   g_cnt[NN];
__device__ int   g_row[NN];
__device__ int   g_cur[NN];
__device__ int   g_part[64];
__device__ int4  g_edge4[(EPAD + 1) / 2];     // 16B-aligned edge storage
#define g_edge ((int2*)g_edge4)
__device__ __half g_x16[NN * CHX];
__device__ __half g_Xp16[NN * CHX];       // prop(x), fp16, layout [n][t*16+f]
__device__ float g_h[NN * HH];
__device__ __half g_h16[NN * HH];
__device__ float g_z[NN * HH];
__device__ __half g_rh16[NN * HH];
__device__ __half g_Ah16[NN * HH];
__device__ __half g_Arh16[NN * HH];
__device__ __half g_Wzr16[128 * 80];      // n-major: [c][k], c<64 -> Wz, else Wr
__device__ __half g_Wh16[64 * 80];        // n-major: [c][k]
__device__ __half g_hs16[NN * TT * HH];   // [n][t][c] fp16

// ---------------- helpers ----------------
__device__ __forceinline__ float fast_tanh(float x) {
    float y;
    asm("tanh.approx.f32 %0, %1;" : "=f"(y) : "f"(x));
    return y;
}
__device__ __forceinline__ float fast_sigmoid(float x) {
    return 0.5f * fast_tanh(0.5f * x) + 0.5f;
}
__device__ __forceinline__ uint32_t smem_u32(const void* p) {
    return (uint32_t)__cvta_generic_to_shared(p);
}
__device__ __forceinline__ void ldsm_x4(unsigned* r, uint32_t addr) {
    asm volatile("ldmatrix.sync.aligned.m8n8.x4.shared.b16 {%0,%1,%2,%3}, [%4];\n"
                 : "=r"(r[0]), "=r"(r[1]), "=r"(r[2]), "=r"(r[3]) : "r"(addr));
}
__device__ __forceinline__ void ldsm_x2(unsigned* r, uint32_t addr) {
    asm volatile("ldmatrix.sync.aligned.m8n8.x2.shared.b16 {%0,%1}, [%2];\n"
                 : "=r"(r[0]), "=r"(r[1]) : "r"(addr));
}
__device__ __forceinline__ void mma16816(float* d, const unsigned* a, const unsigned* b) {
    asm volatile("mma.sync.aligned.m16n8k16.row.col.f32.f16.f16.f32 "
                 "{%0,%1,%2,%3}, {%4,%5,%6,%7}, {%8,%9}, {%0,%1,%2,%3};\n"
                 : "+f"(d[0]), "+f"(d[1]), "+f"(d[2]), "+f"(d[3])
                 : "r"(a[0]), "r"(a[1]), "r"(a[2]), "r"(a[3]), "r"(b[0]), "r"(b[1]));
}

// gather-propagate one node's 64 channels; paired int4 edge loads (R7 best shape)
__device__ __forceinline__ float2 prop_node(int n, int lane, const __half2* __restrict__ in) {
    int st = g_row[n];
    int cnt = g_cnt[n];
    int pairs = (cnt + 1) >> 1;                 // padded slots are zero-weight
    const int4* ep4 = (const int4*)&g_edge[st]; // st is even -> 16B aligned
    float ax = 0.0f, ay = 0.0f;
    int p = 0;
    for (; p + 2 <= pairs; p += 2) {
        int4 ea = __ldg(&ep4[p]);
        int4 eb = __ldg(&ep4[p + 1]);
        float2 v0 = __half22float2(in[ea.x * 32 + lane]);
        float2 v1 = __half22float2(in[ea.z * 32 + lane]);
        float2 v2 = __half22float2(in[eb.x * 32 + lane]);
        float2 v3 = __half22float2(in[eb.z * 32 + lane]);
        float w0 = __int_as_float(ea.y), w1 = __int_as_float(ea.w);
        float w2 = __int_as_float(eb.y), w3 = __int_as_float(eb.w);
        ax += w0 * v0.x + w1 * v1.x + w2 * v2.x + w3 * v3.x;
        ay += w0 * v0.y + w1 * v1.y + w2 * v2.y + w3 * v3.y;
    }
    for (; p < pairs; p++) {
        int4 ea = __ldg(&ep4[p]);
        float2 v0 = __half22float2(in[ea.x * 32 + lane]);
        float2 v1 = __half22float2(in[ea.z * 32 + lane]);
        float w0 = __int_as_float(ea.y), w1 = __int_as_float(ea.w);
        ax += w0 * v0.x + w1 * v1.x;
        ay += w0 * v0.y + w1 * v1.y;
    }
    float sn = g_self[n];
    float2 v = __half22float2(in[n * 32 + lane]);
    ax += sn * v.x;
    ay += sn * v.y;
    return make_float2(ax, ay);
}

// ---------------- prologue kernels ----------------
__global__ void init_kernel() {
    int i = blockIdx.x * blockDim.x + threadIdx.x;
    if (i < NN) { g_deg[i] = 0.0f; g_cnt[i] = 0; }
}

__global__ void convx_kernel(const float* __restrict__ x) {
    int i = blockIdx.x * blockDim.x + threadIdx.x;
    int i4 = i * 4;
    if (i4 + 3 < NN * CHX) {
        float4 v = __ldg((const float4*)&x[i4]);
        __half2* o = (__half2*)&g_x16[i4];
        o[0] = __floats2half2_rn(v.x, v.y);
        o[1] = __floats2half2_rn(v.z, v.w);
    }
}

__global__ void wcvt_kernel(const float* __restrict__ Wz, const float* __restrict__ Wr,
                            const float* __restrict__ Wh) {
    int idx = blockIdx.x * blockDim.x + threadIdx.x;
    if (idx < 128 * 80) {
        int c = idx / 80, k = idx - c * 80;
        float v = (c < 64) ? Wz[k * 64 + c] : Wr[k * 64 + (c - 64)];
        g_Wzr16[c * 80 + k] = __float2half_rn(v);
    }
    if (idx < 64 * 80) {
        int c = idx / 80, k = idx - c * 80;
        g_Wh16[c * 80 + k] = __float2half_rn(Wh[k * 64 + c]);
    }
}

__global__ void deg_kernel(const int* __restrict__ ei, const float* __restrict__ ew) {
    int e = blockIdx.x * blockDim.x + threadIdx.x;
    if (e >= EE) return;
    int d = ei[EE + e];
    atomicAdd(&g_deg[d], ew[e]);
    atomicAdd(&g_cnt[d], 1);
}

__global__ void dis_kernel() {
    int i = blockIdx.x * blockDim.x + threadIdx.x;
    if (i >= NN) return;
    float r = rsqrtf(g_deg[i] + 1.0f);
    g_dis[i] = r;
    g_self[i] = r * r;
}

// hierarchical scan over EVEN-PADDED counts
__global__ void part_kernel() {
    __shared__ int ws[32];
    int tid = threadIdx.x, lane = tid & 31, wid = tid >> 5;
    int i = blockIdx.x * 1024 + tid;
    int v = (i < NN) ? ((g_cnt[i] + 1) & ~1) : 0;
    #pragma unroll
    for (int o = 16; o; o >>= 1) v += __shfl_xor_sync(0xffffffffu, v, o);
    if (lane == 0) ws[wid] = v;
    __syncthreads();
    if (tid < 32) {
        int s = ws[tid];
        #pragma unroll
        for (int o = 16; o; o >>= 1) s += __shfl_xor_sync(0xffffffffu, s, o);
        if (tid == 0) g_part[blockIdx.x] = s;
    }
}

__global__ void scanpart_kernel() {
    if (threadIdx.x == 0) {
        int run = 0;
        for (int b = 0; b < SCAN_B; b++) { int v = g_part[b]; g_part[b] = run; run += v; }
    }
}

__global__ void offs_kernel() {
    __shared__ int wsum[32];
    int tid = threadIdx.x, lane = tid & 31, wid = tid >> 5;
    int i = blockIdx.x * 1024 + tid;
    int v = (i < NN) ? ((g_cnt[i] + 1) & ~1) : 0;
    int x = v;
    #pragma unroll
    for (int o = 1; o < 32; o <<= 1) {
        int y = __shfl_up_sync(0xffffffffu, x, o);
        if (lane >= o) x += y;
    }
    if (lane == 31) wsum[wid] = x;
    __syncthreads();
    if (tid < 32) {
        int s = wsum[tid];
        #pragma unroll
        for (int o = 1; o < 32; o <<= 1) {
            int y = __shfl_up_sync(0xffffffffu, s, o);
            if (tid >= o) s += y;
        }
        wsum[tid] = s;
    }
    __syncthreads();
    int excl = g_part[blockIdx.x] + x - v + (wid ? wsum[wid - 1] : 0);
    if (i < NN) { g_row[i] = excl; g_cur[i] = excl; }
}

__global__ void fill_kernel(const int* __restrict__ ei, const float* __restrict__ ew) {
    int e = blockIdx.x * blockDim.x + threadIdx.x;
    if (e >= EE) return;
    int s = ei[e];
    int d = ei[EE + e];
    int p = atomicAdd(&g_cur[d], 1);
    float w = g_dis[s] * ew[e] * g_dis[d];
    g_edge[p] = make_int2(s, __float_as_int(w));
}

// zero the pad slot of odd-degree nodes
__global__ void pad_kernel() {
    int i = blockIdx.x * blockDim.x + threadIdx.x;
    if (i >= NN) return;
    int c = g_cnt[i];
    if (c & 1) g_edge[g_row[i] + c] = make_int2(0, 0);
}

// propagate all 192 channels of x once (fp16 gather, paired edges). warp per node.
__global__ __launch_bounds__(256) void prop_x_kernel() {
    int gw = (blockIdx.x * blockDim.x + threadIdx.x) >> 5;
    if (gw >= NN) return;
    int lane = threadIdx.x & 31;
    int st = g_row[gw], cnt = g_cnt[gw];
    int pairs = (cnt + 1) >> 1;
    float acc[6] = {0, 0, 0, 0, 0, 0};
    const int4* ep4 = (const int4*)&g_edge[st];
    for (int p = 0; p < pairs; p++) {
        int4 ea = __ldg(&ep4[p]);
        float w0 = __int_as_float(ea.y), w1 = __int_as_float(ea.w);
        const __half2* r0 = (const __half2*)&g_x16[ea.x * CHX];
        const __half2* r1 = (const __half2*)&g_x16[ea.z * CHX];
        #pragma unroll
        for (int j = 0; j < 3; j++) {
            float2 f0 = __half22float2(r0[lane + 32 * j]);
            float2 f1 = __half22float2(r1[lane + 32 * j]);
            acc[2 * j]     += w0 * f0.x + w1 * f1.x;
            acc[2 * j + 1] += w0 * f0.y + w1 * f1.y;
        }
    }
    float sn = g_self[gw];
    const __half2* xn = (const __half2*)&g_x16[gw * CHX];
    #pragma unroll
    for (int j = 0; j < 3; j++) {
        float2 f0 = __half22float2(xn[lane + 32 * j]);
        #pragma unroll
        for (int k = 0; k < 2; k++) {
            int c = 2 * (lane + 32 * j) + k;      // c = f*12 + t (x layout [n][f][t])
            float v = acc[2 * j + k] + sn * (k ? f0.y : f0.x);
            int f = c / 12;
            int t = c - f * 12;
            g_Xp16[gw * CHX + t * FF + f] = __float2half_rn(v);  // [n][t][f]
        }
    }
}

// ---------------- lean propagation kernel (PDL) ----------------
// which==0: Ah16 = prop(h16); which==1: Arh16 = prop(rh16). Warp per node.
// Low register count -> high occupancy during the latency-bound gather.
__global__ __launch_bounds__(256) void prop64_kernel(int which) {
    cudaGridDependencySynchronize();            // predecessor wrote h16/rh16
    cudaTriggerProgrammaticLaunchCompletion();  // successor may launch + stage statics
    int gw = (blockIdx.x * blockDim.x + threadIdx.x) >> 5;
    if (gw >= NN) return;
    int lane = threadIdx.x & 31;
    const __half2* in = (const __half2*)(which ? g_rh16 : g_h16);
    __half2* out = (__half2*)(which ? g_Arh16 : g_Ah16);
    float2 a = prop_node(gw, lane, in);
    out[gw * 32 + lane] = __floats2half2_rn(a.x, a.y);
}

// ---------------- GEMM kernels (PDL) ----------------
// zr: C[64,128] = [Xp16_t | Ah16] @ [Wz|Wr] (HMMA) -> z, rh16
__global__ __launch_bounds__(256) void zr_kernel(const float* __restrict__ bz,
                                                 const float* __restrict__ br, int t) {
    __shared__ __align__(16) __half As[64 * 88];
    __shared__ __align__(16) __half Bs[128 * 88];
    int tid = threadIdx.x;
    int n0 = blockIdx.x * 64;
    int warp = tid >> 5, lane = tid & 31;

    // static staging before waiting on predecessor
    for (int idx = tid; idx < 1280; idx += 256) {
        int c = idx / 10, q = idx - c * 10;
        *(uint4*)&Bs[c * 88 + q * 8] = *(const uint4*)&g_Wzr16[c * 80 + q * 8];
    }
    for (int idx = tid; idx < 128; idx += 256) {
        int m = idx >> 1, q = idx & 1;
        int n = n0 + m;
        uint4 v = make_uint4(0, 0, 0, 0);
        if (n < NN) v = *(const uint4*)&g_Xp16[n * CHX + t * 16 + q * 8];
        *(uint4*)&As[m * 88 + q * 8] = v;
    }

    cudaGridDependencySynchronize();            // Ah16 complete (t>0)
    cudaTriggerProgrammaticLaunchCompletion();  // prop_rh may launch

    // dynamic staging: Ah16 rows 16..79 (zeros at t==0 since h==0)
    for (int idx = tid; idx < 512; idx += 256) {
        int m = idx >> 3, q = idx & 7;
        int n = n0 + m;
        uint4 v = make_uint4(0, 0, 0, 0);
        if (t != 0 && n < NN) v = *(const uint4*)&g_Ah16[n * HH + q * 8];
        *(uint4*)&As[m * 88 + 16 + q * 8] = v;
    }
    __syncthreads();

    int mi = warp & 3, nh = warp >> 2;    // nh: 0 -> z channels, 1 -> r channels
    int m0 = mi * 16;
    float acc[8][4];
    #pragma unroll
    for (int i = 0; i < 8; i++)
        #pragma unroll
        for (int j = 0; j < 4; j++) acc[i][j] = 0.0f;

    uint32_t a_base = smem_u32(As) + (m0 + (lane & 15)) * 176 + (lane >> 4) * 16;
    uint32_t b_base = smem_u32(Bs) + (nh * 64 + (lane & 7)) * 176 + ((lane >> 3) & 1) * 16;

    #pragma unroll
    for (int ks = 0; ks < 5; ks++) {
        unsigned a[4];
        ldsm_x4(a, a_base + ks * 32);
        #pragma unroll
        for (int nj = 0; nj < 8; nj++) {
            unsigned b[2];
            ldsm_x2(b, b_base + nj * 8 * 176 + ks * 32);
            mma16816(acc[nj], a, b);
        }
    }

    int g = lane >> 2, tig = lane & 3;
    #pragma unroll
    for (int nj = 0; nj < 8; nj++) {
        int c = nh * 64 + nj * 8 + tig * 2;
        bool isz = (c < 64);
        float b0v = isz ? __ldg(&bz[c])     : __ldg(&br[c - 64]);
        float b1v = isz ? __ldg(&bz[c + 1]) : __ldg(&br[c - 63]);
        #pragma unroll
        for (int rr = 0; rr < 2; rr++) {
            int n = n0 + m0 + g + rr * 8;
            if (n < NN) {
                float v0 = fast_sigmoid(acc[nj][rr * 2 + 0] + b0v);
                float v1 = fast_sigmoid(acc[nj][rr * 2 + 1] + b1v);
                if (isz) {
                    g_z[n * HH + c]     = v0;
                    g_z[n * HH + c + 1] = v1;
                } else if (t != 0) {   // t==0: rh = r*0 = 0; upd@t=0 stages zeros
                    int cc = c - 64;
                    float2 hf = __half22float2(((const __half2*)g_h16)[(n * HH + cc) >> 1]);
                    ((__half2*)g_rh16)[(n * HH + cc) >> 1] =
                        __floats2half2_rn(v0 * hf.x, v1 * hf.y);
                }
            }
        }
    }
}

// upd: hc = tanh([Xp16_t | Arh16] @ Wh + bh); h = z*h + (1-z)*hc; hs store
__global__ __launch_bounds__(256) void upd_kernel(const float* __restrict__ bh, int t) {
    __shared__ __align__(16) __half As[64 * 88];
    __shared__ __align__(16) __half Bs[64 * 88];
    int tid = threadIdx.x;
    int n0 = blockIdx.x * 64;
    int warp = tid >> 5, lane = tid & 31;

    for (int idx = tid; idx < 640; idx += 256) {
        int c = idx / 10, q = idx - c * 10;
        *(uint4*)&Bs[c * 88 + q * 8] = *(const uint4*)&g_Wh16[c * 80 + q * 8];
    }
    for (int idx = tid; idx < 128; idx += 256) {
        int m = idx >> 1, q = idx & 1;
        int n = n0 + m;
        uint4 v = make_uint4(0, 0, 0, 0);
        if (n < NN) v = *(const uint4*)&g_Xp16[n * CHX + t * 16 + q * 8];
        *(uint4*)&As[m * 88 + q * 8] = v;
    }

    cudaGridDependencySynchronize();            // Arh16 (t>0) and z complete
    cudaTriggerProgrammaticLaunchCompletion();  // next-step prop_h may launch

    for (int idx = tid; idx < 512; idx += 256) {
        int m = idx >> 3, q = idx & 7;
        int n = n0 + m;
        uint4 v = make_uint4(0, 0, 0, 0);
        if (t != 0 && n < NN) v = *(const uint4*)&g_Arh16[n * HH + q * 8];
        *(uint4*)&As[m * 88 + 16 + q * 8] = v;
    }
    __syncthreads();

    int mi = warp & 3, nh = warp >> 2;
    int m0 = mi * 16;
    float acc[4][4];
    #pragma unroll
    for (int i = 0; i < 4; i++)
        #pragma unroll
        for (int j = 0; j < 4; j++) acc[i][j] = 0.0f;

    uint32_t a_base = smem_u32(As) + (m0 + (lane & 15)) * 176 + (lane >> 4) * 16;
    uint32_t b_base = smem_u32(Bs) + (nh * 32 + (lane & 7)) * 176 + ((lane >> 3) & 1) * 16;

    #pragma unroll
    for (int ks = 0; ks < 5; ks++) {
        unsigned a[4];
        ldsm_x4(a, a_base + ks * 32);
        #pragma unroll
        for (int nj = 0; nj < 4; nj++) {
            unsigned b[2];
            ldsm_x2(b, b_base + nj * 8 * 176 + ks * 32);
            mma16816(acc[nj], a, b);
        }
    }

    int g = lane >> 2, tig = lane & 3;
    #pragma unroll
    for (int nj = 0; nj < 4; nj++) {
        int c = nh * 32 + nj * 8 + tig * 2;
        float b0v = __ldg(&bh[c]), b1v = __ldg(&bh[c + 1]);
        #pragma unroll
        for (int rr = 0; rr < 2; rr++) {
            int n = n0 + m0 + g + rr * 8;
            if (n < NN) {
                float hc0 = fast_tanh(acc[nj][rr * 2 + 0] + b0v);
                float hc1 = fast_tanh(acc[nj][rr * 2 + 1] + b1v);
                float z0 = g_z[n * HH + c], z1 = g_z[n * HH + c + 1];
                float hn0, hn1;
                if (t != 0) {
                    float2 h = *(const float2*)&g_h[n * HH + c];
                    hn0 = z0 * h.x + (1.0f - z0) * hc0;
                    hn1 = z1 * h.y + (1.0f - z1) * hc1;
                } else {           // h == 0
                    hn0 = (1.0f - z0) * hc0;
                    hn1 = (1.0f - z1) * hc1;
                }
                *(float2*)&g_h[n * HH + c] = make_float2(hn0, hn1);
                __half2 hh = __floats2half2_rn(hn0, hn1);
                ((__half2*)g_h16)[(n * HH + c) >> 1] = hh;
                ((__half2*)g_hs16)[(n * (TT * HH) + t * HH + c) >> 1] = hh;
            }
        }
    }
}

// ---------------- attention + FC (fp16 hs, PDL) ----------------
__global__ __launch_bounds__(256) void attn_kernel(const float* __restrict__ Wa, const float* __restrict__ ba,
                                                   const float* __restrict__ cv, const float* __restrict__ Wfc,
                                                   const float* __restrict__ bfc, float* __restrict__ out) {
    __shared__ float Wa_s[4096];
    __shared__ float ba_s[64], cv_s[64], fc_s[64];
    __shared__ float al_s[8][TT];
    int tid = threadIdx.x;
    for (int i = tid; i < 4096; i += 256) Wa_s[i] = Wa[i];
    if (tid < 64) { ba_s[tid] = ba[tid]; cv_s[tid] = cv[tid]; fc_s[tid] = Wfc[tid]; }

    cudaGridDependencySynchronize();   // wait for last upd's hs16 writes
    __syncthreads();

    int warp = tid >> 5, lane = tid & 31;
    int n = blockIdx.x * 8 + warp;
    if (n >= NN) return;
    const uint32_t* hb = (const uint32_t*)&g_hs16[n * (TT * HH)];  // 32 half2 per t

    for (int t = 0; t < TT; t++) {
        uint32_t hraw = __ldg(&hb[t * 32 + lane]);  // channels 2*lane, 2*lane+1
        float a0 = ba_s[lane], a1 = ba_s[lane + 32];
        #pragma unroll
        for (int j = 0; j < 32; j++) {
            uint32_t hj = __shfl_sync(0xffffffffu, hraw, j);
            float2 f = __half22float2(*(__half2*)&hj);
            a0 += f.x * Wa_s[(2 * j) * HH + lane]      + f.y * Wa_s[(2 * j + 1) * HH + lane];
            a1 += f.x * Wa_s[(2 * j) * HH + lane + 32] + f.y * Wa_s[(2 * j + 1) * HH + lane + 32];
        }
        float al = fast_tanh(a0) * cv_s[lane] + fast_tanh(a1) * cv_s[lane + 32];
        #pragma unroll
        for (int o = 16; o; o >>= 1) al += __shfl_xor_sync(0xffffffffu, al, o);
        if (lane == 0) al_s[warp][t] = al;
    }
    __syncwarp();

    float mx = -1e30f;
    for (int t = 0; t < TT; t++) mx = fmaxf(mx, al_s[warp][t]);
    float ssum = 0.0f;
    for (int t = 0; t < TT; t++) ssum += __expf(al_s[warp][t] - mx);
    float inv = 1.0f / ssum;

    float cx = 0.0f, cy = 0.0f;
    for (int t = 0; t < TT; t++) {
        float w = __expf(al_s[warp][t] - mx) * inv;
        uint32_t hraw = __ldg(&hb[t * 32 + lane]);
        float2 f = __half22float2(*(__half2*)&hraw);
        cx += w * f.x;
        cy += w * f.y;
    }
    float o = cx * fc_s[2 * lane] + cy * fc_s[2 * lane + 1];
    #pragma unroll
    for (int off = 16; off; off >>= 1) o += __shfl_xor_sync(0xffffffffu, o, off);
    if (lane == 0) out[n] = o + bfc[0];
}

// ---------------- launcher ----------------
extern "C" void kernel_launch(void* const* d_in, const int* in_sizes, int n_in,
                              void* d_out, int out_size) {
    const float* x   = (const float*)d_in[0];
    const int*   ei  = (const int*)d_in[1];
    const float* ew  = (const float*)d_in[2];
    const float* Wz  = (const float*)d_in[3];
    const float* bz  = (const float*)d_in[4];
    const float* Wr  = (const float*)d_in[5];
    const float* br  = (const float*)d_in[6];
    const float* Wh  = (const float*)d_in[7];
    const float* bh  = (const float*)d_in[8];
    const float* Wa  = (const float*)d_in[9];
    const float* ba  = (const float*)d_in[10];
    const float* cv  = (const float*)d_in[11];
    const float* Wfc = (const float*)d_in[12];
    const float* bfc = (const float*)d_in[13];
    float* out = (float*)d_out;

    int eb = (EE + 255) / 256;
    int nb = (NN + 255) / 256;
    int wb = (NN * 32 + 255) / 256;       // warp per node
    int gb = (NN + 63) / 64;              // GEMM tiles
    int ab = (NN + 7) / 8;                // attention

    init_kernel<<<nb, 256>>>();
    convx_kernel<<<(NN * CHX / 4 + 255) / 256, 256>>>(x);
    wcvt_kernel<<<(128 * 80 + 255) / 256, 256>>>(Wz, Wr, Wh);
    deg_kernel<<<eb, 256>>>(ei, ew);
    dis_kernel<<<nb, 256>>>();
    part_kernel<<<SCAN_B, 1024>>>();
    scanpart_kernel<<<1, 32>>>();
    offs_kernel<<<SCAN_B, 1024>>>();
    fill_kernel<<<eb, 256>>>(ei, ew);
    pad_kernel<<<nb, 256>>>();
    prop_x_kernel<<<wb, 256>>>();

    // PDL launch config for the GRU loop + attention
    cudaLaunchAttribute pdl_attr[1];
    pdl_attr[0].id = cudaLaunchAttributeProgrammaticStreamSerialization;
    pdl_attr[0].val.programmaticStreamSerializationAllowed = 1;

    cudaLaunchConfig_t cfg = {};
    cfg.blockDim = dim3(256, 1, 1);
    cfg.stream = 0;
    cfg.attrs = pdl_attr;
    cfg.numAttrs = 1;

    for (int t = 0; t < TT; t++) {
        if (t != 0) {
            cfg.gridDim = dim3((unsigned)wb, 1, 1);
            cudaLaunchKernelEx(&cfg, prop64_kernel, 0);   // Ah16 = prop(h16)
        }
        cfg.gridDim = dim3((unsigned)gb, 1, 1);
        cudaLaunchKernelEx(&cfg, zr_kernel, bz, br, t);
        if (t != 0) {
            cfg.gridDim = dim3((unsigned)wb, 1, 1);
            cudaLaunchKernelEx(&cfg, prop64_kernel, 1);   // Arh16 = prop(rh16)
        }
        cfg.gridDim = dim3((unsigned)gb, 1, 1);
        cudaLaunchKernelEx(&cfg, upd_kernel, bh, t);
    }

    cfg.gridDim = dim3((unsigned)ab, 1, 1);
    cudaLaunchKernelEx(&cfg, attn_kernel, Wa, ba, cv, Wfc, bfc, out);
}

// round 14
// speedup vs baseline: 1.5777x; 1.5777x over previous
#include <cuda_runtime.h>
#include <cuda_fp16.h>
#include <cstdint>
#include <math.h>

#define NN 50000
#define FF 16
#define TT 12
#define HH 64
#define EE 1600000
#define CHX 192   // F*T channels of x per node
#define SCAN_B 49 // ceil(NN/1024)
#define EPAD (EE + NN)

// ---------------- scratch (static device arrays; no allocation) ----------------
__device__ float g_deg[NN];
__device__ float g_dis[NN];
__device__ float g_self[NN];
__device__ int   g_cnt[NN];
__device__ int   g_row[NN];
__device__ int   g_cur[NN];
__device__ int   g_part[64];
__device__ int4  g_edge4[(EPAD + 1) / 2];     // 16B-aligned edge storage
#define g_edge ((int2*)g_edge4)
__device__ __half g_x16[NN * CHX];
__device__ __half g_Xp16[NN * CHX];       // prop(x), fp16, layout [n][t*16+f]
__device__ float g_h[NN * HH];
__device__ __half g_h16[NN * HH];
__device__ __half g_z16[NN * HH];
__device__ __half g_rh16[NN * HH];
__device__ __half g_Wzr16[128 * 80];      // n-major: [c][k], c<64 -> Wz, else Wr
__device__ __half g_Wh16[64 * 80];        // n-major: [c][k]
__device__ __half g_hs16[NN * TT * HH];   // [n][t][c] fp16

// ---------------- helpers ----------------
__device__ __forceinline__ float fast_tanh(float x) {
    float y;
    asm("tanh.approx.f32 %0, %1;" : "=f"(y) : "f"(x));
    return y;
}
__device__ __forceinline__ float fast_sigmoid(float x) {
    return 0.5f * fast_tanh(0.5f * x) + 0.5f;
}
__device__ __forceinline__ uint32_t smem_u32(const void* p) {
    return (uint32_t)__cvta_generic_to_shared(p);
}
__device__ __forceinline__ void ldsm_x4(unsigned* r, uint32_t addr) {
    asm volatile("ldmatrix.sync.aligned.m8n8.x4.shared.b16 {%0,%1,%2,%3}, [%4];\n"
                 : "=r"(r[0]), "=r"(r[1]), "=r"(r[2]), "=r"(r[3]) : "r"(addr));
}
__device__ __forceinline__ void ldsm_x2(unsigned* r, uint32_t addr) {
    asm volatile("ldmatrix.sync.aligned.m8n8.x2.shared.b16 {%0,%1}, [%2];\n"
                 : "=r"(r[0]), "=r"(r[1]) : "r"(addr));
}
__device__ __forceinline__ void mma16816(float* d, const unsigned* a, const unsigned* b) {
    asm volatile("mma.sync.aligned.m16n8k16.row.col.f32.f16.f16.f32 "
                 "{%0,%1,%2,%3}, {%4,%5,%6,%7}, {%8,%9}, {%0,%1,%2,%3};\n"
                 : "+f"(d[0]), "+f"(d[1]), "+f"(d[2]), "+f"(d[3])
                 : "r"(a[0]), "r"(a[1]), "r"(a[2]), "r"(a[3]), "r"(b[0]), "r"(b[1]));
}

// gather-propagate one node's 64 channels; paired int4 edge loads (R7 best shape)
__device__ __forceinline__ float2 prop_node(int n, int lane, const __half2* __restrict__ in) {
    int st = g_row[n];
    int cnt = g_cnt[n];
    int pairs = (cnt + 1) >> 1;                 // padded slots are zero-weight
    const int4* ep4 = (const int4*)&g_edge[st]; // st is even -> 16B aligned
    float ax = 0.0f, ay = 0.0f;
    int p = 0;
    for (; p + 2 <= pairs; p += 2) {
        int4 ea = __ldg(&ep4[p]);
        int4 eb = __ldg(&ep4[p + 1]);
        float2 v0 = __half22float2(in[ea.x * 32 + lane]);
        float2 v1 = __half22float2(in[ea.z * 32 + lane]);
        float2 v2 = __half22float2(in[eb.x * 32 + lane]);
        float2 v3 = __half22float2(in[eb.z * 32 + lane]);
        float w0 = __int_as_float(ea.y), w1 = __int_as_float(ea.w);
        float w2 = __int_as_float(eb.y), w3 = __int_as_float(eb.w);
        ax += w0 * v0.x + w1 * v1.x + w2 * v2.x + w3 * v3.x;
        ay += w0 * v0.y + w1 * v1.y + w2 * v2.y + w3 * v3.y;
    }
    for (; p < pairs; p++) {
        int4 ea = __ldg(&ep4[p]);
        float2 v0 = __half22float2(in[ea.x * 32 + lane]);
        float2 v1 = __half22float2(in[ea.z * 32 + lane]);
        float w0 = __int_as_float(ea.y), w1 = __int_as_float(ea.w);
        ax += w0 * v0.x + w1 * v1.x;
        ay += w0 * v0.y + w1 * v1.y;
    }
    float sn = g_self[n];
    float2 v = __half22float2(in[n * 32 + lane]);
    ax += sn * v.x;
    ay += sn * v.y;
    return make_float2(ax, ay);
}

// ---------------- prologue kernels ----------------
__global__ void init_kernel() {
    int i = blockIdx.x * blockDim.x + threadIdx.x;
    if (i < NN) { g_deg[i] = 0.0f; g_cnt[i] = 0; }
}

// fused: x fp32->fp16 conversion + weight transposes
__global__ void cvt_kernel(const float* __restrict__ x, const float* __restrict__ Wz,
                           const float* __restrict__ Wr, const float* __restrict__ Wh) {
    int i = blockIdx.x * blockDim.x + threadIdx.x;
    int i4 = i * 4;
    if (i4 + 3 < NN * CHX) {
        float4 v = __ldg((const float4*)&x[i4]);
        __half2* o = (__half2*)&g_x16[i4];
        o[0] = __floats2half2_rn(v.x, v.y);
        o[1] = __floats2half2_rn(v.z, v.w);
    }
    if (i < 128 * 80) {
        int c = i / 80, k = i - c * 80;
        float v = (c < 64) ? Wz[k * 64 + c] : Wr[k * 64 + (c - 64)];
        g_Wzr16[c * 80 + k] = __float2half_rn(v);
    }
    if (i < 64 * 80) {
        int c = i / 80, k = i - c * 80;
        g_Wh16[c * 80 + k] = __float2half_rn(Wh[k * 64 + c]);
    }
}

__global__ void deg_kernel(const int* __restrict__ ei, const float* __restrict__ ew) {
    int e = blockIdx.x * blockDim.x + threadIdx.x;
    if (e >= EE) return;
    int d = ei[EE + e];
    atomicAdd(&g_deg[d], ew[e]);
    atomicAdd(&g_cnt[d], 1);
}

// fused: dis/self computation + per-block scan partials (EVEN-PADDED counts)
__global__ void part_kernel() {
    __shared__ int ws[32];
    int tid = threadIdx.x, lane = tid & 31, wid = tid >> 5;
    int i = blockIdx.x * 1024 + tid;
    if (i < NN) {
        float r = rsqrtf(g_deg[i] + 1.0f);
        g_dis[i] = r;
        g_self[i] = r * r;
    }
    int v = (i < NN) ? ((g_cnt[i] + 1) & ~1) : 0;
    #pragma unroll
    for (int o = 16; o; o >>= 1) v += __shfl_xor_sync(0xffffffffu, v, o);
    if (lane == 0) ws[wid] = v;
    __syncthreads();
    if (tid < 32) {
        int s = ws[tid];
        #pragma unroll
        for (int o = 16; o; o >>= 1) s += __shfl_xor_sync(0xffffffffu, s, o);
        if (tid == 0) g_part[blockIdx.x] = s;
    }
}

__global__ void scanpart_kernel() {
    if (threadIdx.x == 0) {
        int run = 0;
        for (int b = 0; b < SCAN_B; b++) { int v = g_part[b]; g_part[b] = run; run += v; }
    }
}

__global__ void offs_kernel() {
    __shared__ int wsum[32];
    int tid = threadIdx.x, lane = tid & 31, wid = tid >> 5;
    int i = blockIdx.x * 1024 + tid;
    int v = (i < NN) ? ((g_cnt[i] + 1) & ~1) : 0;
    int x = v;
    #pragma unroll
    for (int o = 1; o < 32; o <<= 1) {
        int y = __shfl_up_sync(0xffffffffu, x, o);
        if (lane >= o) x += y;
    }
    if (lane == 31) wsum[wid] = x;
    __syncthreads();
    if (tid < 32) {
        int s = wsum[tid];
        #pragma unroll
        for (int o = 1; o < 32; o <<= 1) {
            int y = __shfl_up_sync(0xffffffffu, s, o);
            if (tid >= o) s += y;
        }
        wsum[tid] = s;
    }
    __syncthreads();
    int excl = g_part[blockIdx.x] + x - v + (wid ? wsum[wid - 1] : 0);
    if (i < NN) { g_row[i] = excl; g_cur[i] = excl; }
}

__global__ void fill_kernel(const int* __restrict__ ei, const float* __restrict__ ew) {
    int e = blockIdx.x * blockDim.x + threadIdx.x;
    if (e >= EE) return;
    int s = ei[e];
    int d = ei[EE + e];
    int p = atomicAdd(&g_cur[d], 1);
    float w = g_dis[s] * ew[e] * g_dis[d];
    g_edge[p] = make_int2(s, __float_as_int(w));
}

// propagate all 192 channels of x once (fp16 gather, paired edges). warp per node.
// pad fused: warp leader zeroes its node's odd pad slot before gathering.
__global__ __launch_bounds__(256) void prop_x_kernel() {
    int gw = (blockIdx.x * blockDim.x + threadIdx.x) >> 5;
    if (gw >= NN) return;
    int lane = threadIdx.x & 31;
    int st = g_row[gw], cnt = g_cnt[gw];
    if (lane == 0 && (cnt & 1)) g_edge[st + cnt] = make_int2(0, 0);
    __syncwarp();
    int pairs = (cnt + 1) >> 1;
    float acc[6] = {0, 0, 0, 0, 0, 0};
    const int4* ep4 = (const int4*)&g_edge[st];
    for (int p = 0; p < pairs; p++) {
        int4 ea = __ldg(&ep4[p]);
        float w0 = __int_as_float(ea.y), w1 = __int_as_float(ea.w);
        const __half2* r0 = (const __half2*)&g_x16[ea.x * CHX];
        const __half2* r1 = (const __half2*)&g_x16[ea.z * CHX];
        #pragma unroll
        for (int j = 0; j < 3; j++) {
            float2 f0 = __half22float2(r0[lane + 32 * j]);
            float2 f1 = __half22float2(r1[lane + 32 * j]);
            acc[2 * j]     += w0 * f0.x + w1 * f1.x;
            acc[2 * j + 1] += w0 * f0.y + w1 * f1.y;
        }
    }
    float sn = g_self[gw];
    const __half2* xn = (const __half2*)&g_x16[gw * CHX];
    #pragma unroll
    for (int j = 0; j < 3; j++) {
        float2 f0 = __half22float2(xn[lane + 32 * j]);
        #pragma unroll
        for (int k = 0; k < 2; k++) {
            int c = 2 * (lane + 32 * j) + k;      // c = f*12 + t (x layout [n][f][t])
            float v = acc[2 * j + k] + sn * (k ? f0.y : f0.x);
            int f = c / 12;
            int t = c - f * 12;
            g_Xp16[gw * CHX + t * FF + f] = __float2half_rn(v);  // [n][t][f]
        }
    }
}

// ---------------- fused prop + gate kernels (PDL-enabled, t=0 prop-free) ----------------
// A: stage static, sync, prop(h16) [t>0] or zeros [t==0] -> smem rows 16..79,
//    trigger successor, HMMA epilogue -> z16, rh16
__global__ __launch_bounds__(256, 3) void prop_zr_kernel(const float* __restrict__ bz,
                                                         const float* __restrict__ br, int t) {
    __shared__ __align__(16) __half As[64 * 88];
    __shared__ __align__(16) __half Bs[128 * 88];
    int tid = threadIdx.x;
    int n0 = blockIdx.x * 64;
    int warp = tid >> 5, lane = tid & 31;

    // stage static inputs (weights + Xp) BEFORE waiting on predecessor
    for (int idx = tid; idx < 1280; idx += 256) {
        int c = idx / 10, q = idx - c * 10;
        *(uint4*)&Bs[c * 88 + q * 8] = *(const uint4*)&g_Wzr16[c * 80 + q * 8];
    }
    for (int idx = tid; idx < 128; idx += 256) {
        int m = idx >> 1, q = idx & 1;
        int n = n0 + m;
        uint4 v = make_uint4(0, 0, 0, 0);
        if (n < NN) v = *(const uint4*)&g_Xp16[n * CHX + t * 16 + q * 8];
        *(uint4*)&As[m * 88 + q * 8] = v;
    }

    if (t != 0) {
        cudaGridDependencySynchronize();   // wait for predecessor's h16 writes
        #pragma unroll 1
        for (int i = 0; i < 8; i++) {
            int m = warp * 8 + i;
            int n = n0 + m;
            float2 a = make_float2(0.0f, 0.0f);
            if (n < NN) a = prop_node(n, lane, (const __half2*)g_h16);
            ((__half2*)&As[m * 88 + 16])[lane] = __floats2half2_rn(a.x, a.y);
        }
    } else {
        // h == 0: A rows 16..79 are zero
        for (int idx = tid; idx < 512; idx += 256) {
            int m = idx >> 3, q = idx & 7;
            *(uint4*)&As[m * 88 + 16 + q * 8] = make_uint4(0, 0, 0, 0);
        }
    }
    __syncthreads();
    cudaTriggerProgrammaticLaunchCompletion();  // successor may launch + stage now

    int mi = warp & 3, nh = warp >> 2;    // nh: 0 -> z channels, 1 -> r channels
    int m0 = mi * 16;
    float acc[8][4];
    #pragma unroll
    for (int i = 0; i < 8; i++)
        #pragma unroll
        for (int j = 0; j < 4; j++) acc[i][j] = 0.0f;

    uint32_t a_base = smem_u32(As) + (m0 + (lane & 15)) * 176 + (lane >> 4) * 16;
    uint32_t b_base = smem_u32(Bs) + (nh * 64 + (lane & 7)) * 176 + ((lane >> 3) & 1) * 16;

    #pragma unroll
    for (int ks = 0; ks < 5; ks++) {
        unsigned a[4];
        ldsm_x4(a, a_base + ks * 32);
        #pragma unroll
        for (int nj = 0; nj < 8; nj++) {
            unsigned b[2];
            ldsm_x2(b, b_base + nj * 8 * 176 + ks * 32);
            mma16816(acc[nj], a, b);
        }
    }

    int g = lane >> 2, tig = lane & 3;
    #pragma unroll
    for (int nj = 0; nj < 8; nj++) {
        int c = nh * 64 + nj * 8 + tig * 2;
        bool isz = (c < 64);
        float b0v = isz ? __ldg(&bz[c])     : __ldg(&br[c - 64]);
        float b1v = isz ? __ldg(&bz[c + 1]) : __ldg(&br[c - 63]);
        #pragma unroll
        for (int rr = 0; rr < 2; rr++) {
            int n = n0 + m0 + g + rr * 8;
            if (n < NN) {
                float v0 = fast_sigmoid(acc[nj][rr * 2 + 0] + b0v);
                float v1 = fast_sigmoid(acc[nj][rr * 2 + 1] + b1v);
                if (isz) {
                    ((__half2*)g_z16)[(n * HH + c) >> 1] = __floats2half2_rn(v0, v1);
                } else if (t != 0) {   // t==0: rh = r*0 = 0; upd@t=0 stages zeros
                    int cc = c - 64;
                    float2 hf = __half22float2(((const __half2*)g_h16)[(n * HH + cc) >> 1]);
                    ((__half2*)g_rh16)[(n * HH + cc) >> 1] =
                        __floats2half2_rn(v0 * hf.x, v1 * hf.y);
                }
            }
        }
    }
}

// B: stage static, sync, prop(rh16) [t>0] or zeros [t==0] -> smem, trigger,
//    HMMA epilogue -> h update + hs store
__global__ __launch_bounds__(256, 4) void prop_upd_kernel(const float* __restrict__ bh, int t) {
    __shared__ __align__(16) __half As[64 * 88];
    __shared__ __align__(16) __half Bs[64 * 88];
    int tid = threadIdx.x;
    int n0 = blockIdx.x * 64;
    int warp = tid >> 5, lane = tid & 31;

    for (int idx = tid; idx < 640; idx += 256) {
        int c = idx / 10, q = idx - c * 10;
        *(uint4*)&Bs[c * 88 + q * 8] = *(const uint4*)&g_Wh16[c * 80 + q * 8];
    }
    for (int idx = tid; idx < 128; idx += 256) {
        int m = idx >> 1, q = idx & 1;
        int n = n0 + m;
        uint4 v = make_uint4(0, 0, 0, 0);
        if (n < NN) v = *(const uint4*)&g_Xp16[n * CHX + t * 16 + q * 8];
        *(uint4*)&As[m * 88 + q * 8] = v;
    }

    cudaGridDependencySynchronize();   // wait for zr's z (and rh16 when t>0) writes

    if (t != 0) {
        #pragma unroll 1
        for (int i = 0; i < 8; i++) {
            int m = warp * 8 + i;
            int n = n0 + m;
            float2 a = make_float2(0.0f, 0.0f);
            if (n < NN) a = prop_node(n, lane, (const __half2*)g_rh16);
            ((__half2*)&As[m * 88 + 16])[lane] = __floats2half2_rn(a.x, a.y);
        }
    } else {
        for (int idx = tid; idx < 512; idx += 256) {
            int m = idx >> 3, q = idx & 7;
            *(uint4*)&As[m * 88 + 16 + q * 8] = make_uint4(0, 0, 0, 0);
        }
    }
    __syncthreads();
    cudaTriggerProgrammaticLaunchCompletion();

    int mi = warp & 3, nh = warp >> 2;
    int m0 = mi * 16;
    float acc[4][4];
    #pragma unroll
    for (int i = 0; i < 4; i++)
        #pragma unroll
        for (int j = 0; j < 4; j++) acc[i][j] = 0.0f;

    uint32_t a_base = smem_u32(As) + (m0 + (lane & 15)) * 176 + (lane >> 4) * 16;
    uint32_t b_base = smem_u32(Bs) + (nh * 32 + (lane & 7)) * 176 + ((lane >> 3) & 1) * 16;

    #pragma unroll
    for (int ks = 0; ks < 5; ks++) {
        unsigned a[4];
        ldsm_x4(a, a_base + ks * 32);
        #pragma unroll
        for (int nj = 0; nj < 4; nj++) {
            unsigned b[2];
            ldsm_x2(b, b_base + nj * 8 * 176 + ks * 32);
            mma16816(acc[nj], a, b);
        }
    }

    int g = lane >> 2, tig = lane & 3;
    #pragma unroll
    for (int nj = 0; nj < 4; nj++) {
        int c = nh * 32 + nj * 8 + tig * 2;
        float b0v = __ldg(&bh[c]), b1v = __ldg(&bh[c + 1]);
        #pragma unroll
        for (int rr = 0; rr < 2; rr++) {
            int n = n0 + m0 + g + rr * 8;
            if (n < NN) {
                float hc0 = fast_tanh(acc[nj][rr * 2 + 0] + b0v);
                float hc1 = fast_tanh(acc[nj][rr * 2 + 1] + b1v);
                float2 zf = __half22float2(((const __half2*)g_z16)[(n * HH + c) >> 1]);
                float hn0, hn1;
                if (t != 0) {
                    float2 h = *(const float2*)&g_h[n * HH + c];
                    hn0 = zf.x * h.x + (1.0f - zf.x) * hc0;
                    hn1 = zf.y * h.y + (1.0f - zf.y) * hc1;
                } else {           // h == 0
                    hn0 = (1.0f - zf.x) * hc0;
                    hn1 = (1.0f - zf.y) * hc1;
                }
                *(float2*)&g_h[n * HH + c] = make_float2(hn0, hn1);
                __half2 hh = __floats2half2_rn(hn0, hn1);
                ((__half2*)g_h16)[(n * HH + c) >> 1] = hh;
                ((__half2*)g_hs16)[(n * (TT * HH) + t * HH + c) >> 1] = hh;
            }
        }
    }
}

// ---------------- attention + FC (fp16 hs, PDL) ----------------
__global__ __launch_bounds__(256) void attn_kernel(const float* __restrict__ Wa, const float* __restrict__ ba,
                                                   const float* __restrict__ cv, const float* __restrict__ Wfc,
                                                   const float* __restrict__ bfc, float* __restrict__ out) {
    __shared__ float Wa_s[4096];
    __shared__ float ba_s[64], cv_s[64], fc_s[64];
    __shared__ float al_s[8][TT];
    int tid = threadIdx.x;
    for (int i = tid; i < 4096; i += 256) Wa_s[i] = Wa[i];
    if (tid < 64) { ba_s[tid] = ba[tid]; cv_s[tid] = cv[tid]; fc_s[tid] = Wfc[tid]; }

    cudaGridDependencySynchronize();   // wait for last upd's hs16 writes
    __syncthreads();

    int warp = tid >> 5, lane = tid & 31;
    int n = blockIdx.x * 8 + warp;
    if (n >= NN) return;
    const uint32_t* hb = (const uint32_t*)&g_hs16[n * (TT * HH)];  // 32 half2 per t

    for (int t = 0; t < TT; t++) {
        uint32_t hraw = __ldg(&hb[t * 32 + lane]);  // channels 2*lane, 2*lane+1
        float a0 = ba_s[lane], a1 = ba_s[lane + 32];
        #pragma unroll
        for (int j = 0; j < 32; j++) {
            uint32_t hj = __shfl_sync(0xffffffffu, hraw, j);
            float2 f = __half22float2(*(__half2*)&hj);
            a0 += f.x * Wa_s[(2 * j) * HH + lane]      + f.y * Wa_s[(2 * j + 1) * HH + lane];
            a1 += f.x * Wa_s[(2 * j) * HH + lane + 32] + f.y * Wa_s[(2 * j + 1) * HH + lane + 32];
        }
        float al = fast_tanh(a0) * cv_s[lane] + fast_tanh(a1) * cv_s[lane + 32];
        #pragma unroll
        for (int o = 16; o; o >>= 1) al += __shfl_xor_sync(0xffffffffu, al, o);
        if (lane == 0) al_s[warp][t] = al;
    }
    __syncwarp();

    float mx = -1e30f;
    for (int t = 0; t < TT; t++) mx = fmaxf(mx, al_s[warp][t]);
    float ssum = 0.0f;
    for (int t = 0; t < TT; t++) ssum += __expf(al_s[warp][t] - mx);
    float inv = 1.0f / ssum;

    float cx = 0.0f, cy = 0.0f;
    for (int t = 0; t < TT; t++) {
        float w = __expf(al_s[warp][t] - mx) * inv;
        uint32_t hraw = __ldg(&hb[t * 32 + lane]);
        float2 f = __half22float2(*(__half2*)&hraw);
        cx += w * f.x;
        cy += w * f.y;
    }
    float o = cx * fc_s[2 * lane] + cy * fc_s[2 * lane + 1];
    #pragma unroll
    for (int off = 16; off; off >>= 1) o += __shfl_xor_sync(0xffffffffu, o, off);
    if (lane == 0) out[n] = o + bfc[0];
}

// ---------------- launcher ----------------
extern "C" void kernel_launch(void* const* d_in, const int* in_sizes, int n_in,
                              void* d_out, int out_size) {
    const float* x   = (const float*)d_in[0];
    const int*   ei  = (const int*)d_in[1];
    const float* ew  = (const float*)d_in[2];
    const float* Wz  = (const float*)d_in[3];
    const float* bz  = (const float*)d_in[4];
    const float* Wr  = (const float*)d_in[5];
    const float* br  = (const float*)d_in[6];
    const float* Wh  = (const float*)d_in[7];
    const float* bh  = (const float*)d_in[8];
    const float* Wa  = (const float*)d_in[9];
    const float* ba  = (const float*)d_in[10];
    const float* cv  = (const float*)d_in[11];
    const float* Wfc = (const float*)d_in[12];
    const float* bfc = (const float*)d_in[13];
    float* out = (float*)d_out;

    int eb = (EE + 255) / 256;
    int nb = (NN + 255) / 256;
    int wb = (NN * 32 + 255) / 256;       // warp per node
    int gb = (NN + 63) / 64;              // fused tiles
    int ab = (NN + 7) / 8;                // attention

    init_kernel<<<nb, 256>>>();
    cvt_kernel<<<(NN * CHX / 4 + 255) / 256, 256>>>(x, Wz, Wr, Wh);
    deg_kernel<<<eb, 256>>>(ei, ew);
    part_kernel<<<SCAN_B, 1024>>>();
    scanpart_kernel<<<1, 32>>>();
    offs_kernel<<<SCAN_B, 1024>>>();
    fill_kernel<<<eb, 256>>>(ei, ew);
    prop_x_kernel<<<wb, 256>>>();

    // PDL launch config for the GRU loop + attention
    cudaLaunchAttribute pdl_attr[1];
    pdl_attr[0].id = cudaLaunchAttributeProgrammaticStreamSerialization;
    pdl_attr[0].val.programmaticStreamSerializationAllowed = 1;

    cudaLaunchConfig_t cfg = {};
    cfg.blockDim = dim3(256, 1, 1);
    cfg.stream = 0;
    cfg.attrs = pdl_attr;
    cfg.numAttrs = 1;

    for (int t = 0; t < TT; t++) {
        cfg.gridDim = dim3((unsigned)gb, 1, 1);
        cudaLaunchKernelEx(&cfg, prop_zr_kernel, bz, br, t);
        cudaLaunchKernelEx(&cfg, prop_upd_kernel, bh, t);
    }

    cfg.gridDim = dim3((unsigned)ab, 1, 1);
    cudaLaunchKernelEx(&cfg, attn_kernel, Wa, ba, cv, Wfc, bfc, out);
}